// round 15
// baseline (speedup 1.0000x reference)
#include <cuda_runtime.h>
#include <cuda_fp16.h>
#include <math.h>
#include <stdint.h>

#define NNODE 100000
#define NP 3
#define NE 800000
#define INF 128
#define NH 4
#define HD 128
#define HID 64
#define PN (NP*NNODE)
#define PE (NP*NE)
#define NEG_SLOPE 0.2f

#define SCAN_ITEMS 1024
#define NB ((PN + SCAN_ITEMS - 1) / SCAN_ITEMS)   // 293
#define MBLK ((NNODE + 127) / 128)                // 782
#define P2BLK ((NNODE + 7) / 8)                   // 12500

// gemm dynamic smem: A 128x132 f32 + 2x B 32x136 f32 (double buffer)
#define BCHUNK (32 * 136)
#define GEMM_SMEM ((128 * 132 + 2 * BCHUNK) * 4)  // 102400 B

// ---------------- device scratch (static, no allocations) ----------------
__device__ __align__(16) __half g_feat[(size_t)NP * NNODE * HD];
__device__ __align__(16) __half g_zh[(size_t)NP * NNODE * HD];
__device__ __align__(16) float g_el[PN * NH];
__device__ __align__(16) float g_er[PN * NH];
__device__ int   g_count[PN];
__device__ int   g_cursor[PN];
__device__ int   g_off[PN];
__device__ int   g_bsums[512];
__device__ int   g_esrc[PE];
__device__ float g_wsum[NP];

// ---------------- helpers ----------------
__device__ __forceinline__ float totf32(float x) {
    uint32_t u; asm("cvt.rna.tf32.f32 %0, %1;" : "=r"(u) : "f"(x));
    return __uint_as_float(u);
}
__device__ __forceinline__ float4 totf32_4(float4 v) {
    return make_float4(totf32(v.x), totf32(v.y), totf32(v.z), totf32(v.w));
}
__device__ __forceinline__ void mma8(float* d, uint32_t a0, uint32_t a1,
                                     uint32_t a2, uint32_t a3,
                                     uint32_t b0, uint32_t b1) {
    asm("mma.sync.aligned.m16n8k8.row.col.f32.tf32.tf32.f32 "
        "{%0,%1,%2,%3},{%4,%5,%6,%7},{%8,%9},{%0,%1,%2,%3};"
        : "+f"(d[0]), "+f"(d[1]), "+f"(d[2]), "+f"(d[3])
        : "r"(a0), "r"(a1), "r"(a2), "r"(a3), "r"(b0), "r"(b1));
}
__device__ __forceinline__ void cpa16(uint32_t dst, const void* src) {
    asm volatile("cp.async.cg.shared.global [%0], [%1], 16;" :: "r"(dst), "l"(src));
}
__device__ __forceinline__ void cpa_commit() {
    asm volatile("cp.async.commit_group;");
}
__device__ __forceinline__ void cpa_wait0() {
    asm volatile("cp.async.wait_group 0;" ::: "memory");
}
__device__ __forceinline__ float tanhfast(float x) {
    float y; asm("tanh.approx.f32 %0, %1;" : "=f"(y) : "f"(x)); return y;
}
__device__ __forceinline__ float pick4(float4 v, int h) {
    float r = v.x;
    r = (h == 1) ? v.y : r;
    r = (h == 2) ? v.z : r;
    r = (h == 3) ? v.w : r;
    return r;
}
__device__ __forceinline__ float lrelu(float e) {
    return fmaxf(e, NEG_SLOPE * e);
}
__device__ __forceinline__ float4 edge_exp(const float* __restrict__ elbase,
                                           int src, float4 er4) {
    float4 el4 = *(const float4*)&elbase[src * NH];
    return make_float4(__expf(lrelu(el4.x + er4.x)),
                       __expf(lrelu(el4.y + er4.y)),
                       __expf(lrelu(el4.z + er4.z)),
                       __expf(lrelu(el4.w + er4.w)));
}

// ---------------- K0: init ----------------
__global__ void k_init() {
    int i = blockIdx.x * blockDim.x + threadIdx.x;
    if (i < PN) { g_count[i] = 0; g_cursor[i] = 0; }
    if (i < NP) g_wsum[i] = 0.f;
}

// ---------------- K1: feat = h @ W_p, A-resident, cp.async dbl-buffered B ----------------
// warp grid 4(M) x 2(N): warp owns 32 rows x 64 cols = 2 m-tiles x 8 n-tiles.
__global__ void __launch_bounds__(256, 2) k_gemm(const float* __restrict__ h,
                                                 const float* __restrict__ W,
                                                 const float* __restrict__ attn_l,
                                                 const float* __restrict__ attn_r) {
    extern __shared__ float sm[];
    float* As = sm;                 // 128 x 132 (full K resident, rna tf32 bits)
    float* Bs = sm + 128 * 132;     // 2 x (32 x 136) double buffer (raw f32 bits)

    const int row0 = blockIdx.x * 128;
    const int tid = threadIdx.x;
    const int w = tid >> 5, lane = tid & 31;
    const int gid = lane >> 2, tig = lane & 3;
    const int wm = w & 3;           // M group (32 rows)
    const int wn = w >> 2;          // N half (64 cols)
    const uint32_t Bs_u = (uint32_t)__cvta_generic_to_shared(Bs);

    // per-thread B staging coords (4 x 16B per chunk)
    const int br[4] = { tid >> 5, (tid + 256) >> 5, (tid + 512) >> 5, (tid + 768) >> 5 };
    const int bq = tid & 31;

    // stage full A tile once (rna tf32)
    for (int i = tid; i < 4096; i += 256) {
        int r = i >> 5, q = i & 31;
        int row = min(row0 + r, NNODE - 1);
        float4 v = *(const float4*)(h + (size_t)row * INF + q * 4);
        *(float4*)&As[r * 132 + q * 4] = totf32_4(v);
    }
    // async-stage B chunk 0 into buf0
#pragma unroll
    for (int t = 0; t < 4; t++)
        cpa16(Bs_u + (uint32_t)(br[t] * 136 + bq * 4) * 4,
              W + (size_t)br[t] * HD + bq * 4);
    cpa_commit();

    const int rbase = row0 + wm * 32;
    const int arow[2] = { (wm * 32 + gid) * 132, (wm * 32 + 16 + gid) * 132 };
    const int cbase = wn * 64;

    float acc[2][8][4];
#pragma unroll
    for (int mt = 0; mt < 2; mt++)
#pragma unroll
        for (int nt = 0; nt < 8; nt++) {
            acc[mt][nt][0] = acc[mt][nt][1] = acc[mt][nt][2] = acc[mt][nt][3] = 0.f;
        }

    for (int c = 0; c < 12; c++) {
        // wait for chunk c copy, make visible block-wide
        cpa_wait0();
        __syncthreads();

        // issue async copy of chunk c+1 into the other buffer
        if (c < 11) {
            const float* Wc = W + (size_t)((c + 1) >> 2) * INF * HD
                                + (size_t)(((c + 1) & 3) * 32) * HD;
            uint32_t nxt = Bs_u + (uint32_t)(((c + 1) & 1) * BCHUNK) * 4;
#pragma unroll
            for (int t = 0; t < 4; t++)
                cpa16(nxt + (uint32_t)(br[t] * 136 + bq * 4) * 4,
                      Wc + (size_t)br[t] * HD + bq * 4);
            cpa_commit();
        }

        const float* curB = Bs + (c & 1) * BCHUNK;
        const int kaBase = (c & 3) * 32;
#pragma unroll
        for (int ks = 0; ks < 4; ks++) {
            int ka = kaBase + ks * 8;
            int kb = ks * 8;
            uint32_t af[2][4];
#pragma unroll
            for (int mt = 0; mt < 2; mt++) {
                af[mt][0] = __float_as_uint(As[arow[mt] + ka + tig]);
                af[mt][1] = __float_as_uint(As[arow[mt] + 8 * 132 + ka + tig]);
                af[mt][2] = __float_as_uint(As[arow[mt] + ka + tig + 4]);
                af[mt][3] = __float_as_uint(As[arow[mt] + 8 * 132 + ka + tig + 4]);
            }
#pragma unroll
            for (int nt = 0; nt < 8; nt++) {
                uint32_t b0 = __float_as_uint(curB[(kb + tig) * 136 + cbase + nt * 8 + gid]);
                uint32_t b1 = __float_as_uint(curB[(kb + tig + 4) * 136 + cbase + nt * 8 + gid]);
                mma8(acc[0][nt], af[0][0], af[0][1], af[0][2], af[0][3], b0, b1);
                mma8(acc[1][nt], af[1][0], af[1][1], af[1][2], af[1][3], b0, b1);
            }
        }

        if ((c & 3) == 3) {
            const int p = c >> 2;
            const float* alp = attn_l + p * HD;
            const float* arp = attn_r + p * HD;
#pragma unroll
            for (int mt = 0; mt < 2; mt++) {
                int r0 = rbase + mt * 16 + gid;
                int r1 = r0 + 8;
                bool ok0 = r0 < NNODE, ok1 = r1 < NNODE;
#pragma unroll
                for (int nt = 0; nt < 8; nt++) {
                    int col = cbase + nt * 8 + tig * 2;
                    if (ok0) *(__half2*)&g_feat[((size_t)p * NNODE + r0) * HD + col] =
                        __floats2half2_rn(acc[mt][nt][0], acc[mt][nt][1]);
                    if (ok1) *(__half2*)&g_feat[((size_t)p * NNODE + r1) * HD + col] =
                        __floats2half2_rn(acc[mt][nt][2], acc[mt][nt][3]);
                }
#pragma unroll
                for (int hl = 0; hl < 2; hl++) {
                    int hd = wn * 2 + hl;
                    float vl0 = 0.f, vl1 = 0.f, vr0 = 0.f, vr1 = 0.f;
#pragma unroll
                    for (int t = 0; t < 4; t++) {
                        int nt = hl * 4 + t;
                        int col = cbase + nt * 8 + tig * 2;
                        float w0 = alp[col], w1 = alp[col + 1];
                        float u0 = arp[col], u1 = arp[col + 1];
                        vl0 += acc[mt][nt][0] * w0 + acc[mt][nt][1] * w1;
                        vl1 += acc[mt][nt][2] * w0 + acc[mt][nt][3] * w1;
                        vr0 += acc[mt][nt][0] * u0 + acc[mt][nt][1] * u1;
                        vr1 += acc[mt][nt][2] * u0 + acc[mt][nt][3] * u1;
                    }
                    vl0 += __shfl_xor_sync(0xffffffffu, vl0, 1); vl0 += __shfl_xor_sync(0xffffffffu, vl0, 2);
                    vl1 += __shfl_xor_sync(0xffffffffu, vl1, 1); vl1 += __shfl_xor_sync(0xffffffffu, vl1, 2);
                    vr0 += __shfl_xor_sync(0xffffffffu, vr0, 1); vr0 += __shfl_xor_sync(0xffffffffu, vr0, 2);
                    vr1 += __shfl_xor_sync(0xffffffffu, vr1, 1); vr1 += __shfl_xor_sync(0xffffffffu, vr1, 2);
                    if (tig == 0) {
                        if (ok0) { g_el[(p * NNODE + r0) * NH + hd] = vl0;
                                   g_er[(p * NNODE + r0) * NH + hd] = vr0; }
                        if (ok1) { g_el[(p * NNODE + r1) * NH + hd] = vl1;
                                   g_er[(p * NNODE + r1) * NH + hd] = vr1; }
                    }
                }
            }
#pragma unroll
            for (int mt = 0; mt < 2; mt++)
#pragma unroll
                for (int nt = 0; nt < 8; nt++) {
                    acc[mt][nt][0] = acc[mt][nt][1] = acc[mt][nt][2] = acc[mt][nt][3] = 0.f;
                }
        }
    }
}

// ---------------- K2: count in-degree ----------------
__global__ void k_count(const int* __restrict__ edge_dst) {
    int i = blockIdx.x * blockDim.x + threadIdx.x;
    if (i >= PE) return;
    int p = i / NE;
    atomicAdd(&g_count[p * NNODE + edge_dst[i]], 1);
}

// ---------------- scan (3 kernels) ----------------
__global__ void k_scan_blocks() {
    __shared__ int s[256];
    int base = blockIdx.x * SCAN_ITEMS;
    int t = threadIdx.x;
    int v = 0;
#pragma unroll
    for (int i = 0; i < 4; i++) {
        int idx = base + t * 4 + i;
        if (idx < PN) v += g_count[idx];
    }
    s[t] = v; __syncthreads();
    for (int o = 128; o > 0; o >>= 1) {
        if (t < o) s[t] += s[t + o];
        __syncthreads();
    }
    if (t == 0) g_bsums[blockIdx.x] = s[0];
}

__global__ void k_scan_bsums() {
    __shared__ int s[512];
    int t = threadIdx.x;
    int v = (t < NB) ? g_bsums[t] : 0;
    s[t] = v; __syncthreads();
    for (int o = 1; o < 512; o <<= 1) {
        int x = (t >= o) ? s[t - o] : 0;
        __syncthreads();
        s[t] += x;
        __syncthreads();
    }
    if (t < NB) g_bsums[t] = s[t] - v;  // exclusive
}

__global__ void k_scan_final() {
    __shared__ int s[256];
    int base = blockIdx.x * SCAN_ITEMS;
    int t = threadIdx.x;
    int loc[4]; int sum = 0;
#pragma unroll
    for (int i = 0; i < 4; i++) {
        int idx = base + t * 4 + i;
        loc[i] = (idx < PN) ? g_count[idx] : 0;
        sum += loc[i];
    }
    s[t] = sum; __syncthreads();
    for (int o = 1; o < 256; o <<= 1) {
        int x = (t >= o) ? s[t - o] : 0;
        __syncthreads();
        s[t] += x;
        __syncthreads();
    }
    int ex = s[t] - sum + g_bsums[blockIdx.x];
#pragma unroll
    for (int i = 0; i < 4; i++) {
        int idx = base + t * 4 + i;
        if (idx < PN) { g_off[idx] = ex; ex += loc[i]; }
    }
}

// ---------------- K3: scatter src by dst ----------------
__global__ void k_scatter(const int* __restrict__ edge_src,
                          const int* __restrict__ edge_dst) {
    int i = blockIdx.x * blockDim.x + threadIdx.x;
    if (i >= PE) return;
    int p = i / NE;
    int seg = p * NNODE + edge_dst[i];
    int pos = atomicAdd(&g_cursor[seg], 1);
    g_esrc[g_off[seg] + pos] = edge_src[i];
}

// ---------------- K4: fused GAT softmax + aggregate (one metapath) ----------------
__global__ void __launch_bounds__(256) k_p2(const float* __restrict__ bias, int p) {
    __shared__ float sex[8 * 128];   // per-warp 32 x float4 ex table
    int node = (blockIdx.x * blockDim.x + threadIdx.x) >> 5;
    if (node >= NNODE) return;
    const int wid = (threadIdx.x >> 5);
    const int lane = threadIdx.x & 31;
    const int seg = p * NNODE + node;
    const int start = g_off[seg];
    const int cnt = g_count[seg];
    const int hd = lane >> 3;
    float* myex = &sex[wid * 128];
    const float* elbase = g_el + (size_t)p * NNODE * NH;
    const __half* fb = g_feat + (size_t)p * NNODE * HD;
    const float4 er4 = *(const float4*)&g_er[seg * NH];

    float4 a = *(const float4*)&bias[p * HD + lane * 4];

    if (cnt > 0 && cnt <= 32) {
        int src = 0;
        float4 ex = make_float4(0.f, 0.f, 0.f, 0.f);
        if (lane < cnt) {
            src = g_esrc[start + lane];
            ex = edge_exp(elbase, src, er4);
        }
        *(float4*)&myex[lane * 4] = ex;
        __syncwarp();
        float4 s = ex;
#pragma unroll
        for (int o = 16; o > 0; o >>= 1) {
            s.x += __shfl_xor_sync(0xffffffffu, s.x, o);
            s.y += __shfl_xor_sync(0xffffffffu, s.y, o);
            s.z += __shfl_xor_sync(0xffffffffu, s.z, o);
            s.w += __shfl_xor_sync(0xffffffffu, s.w, o);
        }
        float rs = 1.f / fmaxf(pick4(s, hd), 1e-9f);
#pragma unroll 4
        for (int j = 0; j < cnt; j++) {
            int sj = __shfl_sync(0xffffffffu, src, j);
            float wgt = myex[j * 4 + hd] * rs;
            uint2 fv = *(const uint2*)&fb[(size_t)sj * HD + lane * 4];
            float2 g01 = __half22float2(*(__half2*)&fv.x);
            float2 g23 = __half22float2(*(__half2*)&fv.y);
            a.x += wgt * g01.x; a.y += wgt * g01.y;
            a.z += wgt * g23.x; a.w += wgt * g23.y;
        }
    } else if (cnt > 32) {
        float4 s = make_float4(0.f, 0.f, 0.f, 0.f);
        for (int c0 = 0; c0 < cnt; c0 += 32) {
            if (c0 + lane < cnt) {
                int src = g_esrc[start + c0 + lane];
                float4 ex = edge_exp(elbase, src, er4);
                s.x += ex.x; s.y += ex.y; s.z += ex.z; s.w += ex.w;
            }
        }
#pragma unroll
        for (int o = 16; o > 0; o >>= 1) {
            s.x += __shfl_xor_sync(0xffffffffu, s.x, o);
            s.y += __shfl_xor_sync(0xffffffffu, s.y, o);
            s.z += __shfl_xor_sync(0xffffffffu, s.z, o);
            s.w += __shfl_xor_sync(0xffffffffu, s.w, o);
        }
        float rs = 1.f / fmaxf(pick4(s, hd), 1e-9f);
        for (int c0 = 0; c0 < cnt; c0 += 32) {
            int src = 0;
            float4 ex = make_float4(0.f, 0.f, 0.f, 0.f);
            if (c0 + lane < cnt) {
                src = g_esrc[start + c0 + lane];
                ex = edge_exp(elbase, src, er4);
            }
            *(float4*)&myex[lane * 4] = ex;
            __syncwarp();
            int lim = min(32, cnt - c0);
            for (int j = 0; j < lim; j++) {
                int sj = __shfl_sync(0xffffffffu, src, j);
                float wgt = myex[j * 4 + hd] * rs;
                uint2 fv = *(const uint2*)&fb[(size_t)sj * HD + lane * 4];
                float2 g01 = __half22float2(*(__half2*)&fv.x);
                float2 g23 = __half22float2(*(__half2*)&fv.y);
                a.x += wgt * g01.x; a.y += wgt * g01.y;
                a.z += wgt * g23.x; a.w += wgt * g23.y;
            }
            __syncwarp();
        }
    }
    __half2 z01 = __floats2half2_rn(a.x, a.y);
    __half2 z23 = __floats2half2_rn(a.z, a.w);
    uint2 zv;
    zv.x = *(uint32_t*)&z01;
    zv.y = *(uint32_t*)&z23;
    *(uint2*)&g_zh[(size_t)seg * HD + lane * 4] = zv;
}

// ---------------- K5: semantic score (one metapath) ----------------
__global__ void __launch_bounds__(256) k_sem(const float* __restrict__ sa_w1,
                                             const float* __restrict__ sa_b1,
                                             const float* __restrict__ sa_w2,
                                             int p) {
    __shared__ float Zs[128 * 36];
    __shared__ float W1s[32 * 72];
    __shared__ float s_sum;

    const int row0 = blockIdx.x * 128;
    const int tid = threadIdx.x;
    const int w = tid >> 5, lane = tid & 31;
    const int gid = lane >> 2, tig = lane & 3;
    if (tid == 0) s_sum = 0.f;

    float acc[8][4];
#pragma unroll
    for (int t = 0; t < 8; t++) { acc[t][0] = acc[t][1] = acc[t][2] = acc[t][3] = 0.f; }

    const __half* zb = g_zh + (size_t)p * NNODE * HD;
    for (int kc = 0; kc < 4; kc++) {
        for (int i = tid; i < 1024; i += 256) {
            int r = i >> 3, q = i & 7;
            float4 o = make_float4(0.f, 0.f, 0.f, 0.f);
            if (row0 + r < NNODE) {
                uint2 hv = *(const uint2*)(zb + (size_t)(row0 + r) * HD + kc * 32 + q * 4);
                float2 f01 = __half22float2(*(__half2*)&hv.x);
                float2 f23 = __half22float2(*(__half2*)&hv.y);
                o = make_float4(totf32(f01.x), totf32(f01.y), totf32(f23.x), totf32(f23.y));
            }
            *(float4*)&Zs[r * 36 + q * 4] = o;
        }
        for (int i = tid; i < 512; i += 256) {
            int r = i >> 4, q = i & 15;
            float4 v = *(const float4*)(sa_w1 + (size_t)(kc * 32 + r) * HID + q * 4);
            *(float4*)&W1s[r * 72 + q * 4] = totf32_4(v);
        }
        __syncthreads();

#pragma unroll
        for (int ks = 0; ks < 4; ks++) {
            int kb = ks * 8;
            uint32_t a0 = __float_as_uint(Zs[(w * 16 + gid) * 36 + kb + tig]);
            uint32_t a1 = __float_as_uint(Zs[(w * 16 + gid + 8) * 36 + kb + tig]);
            uint32_t a2 = __float_as_uint(Zs[(w * 16 + gid) * 36 + kb + tig + 4]);
            uint32_t a3 = __float_as_uint(Zs[(w * 16 + gid + 8) * 36 + kb + tig + 4]);
#pragma unroll
            for (int nt = 0; nt < 8; nt++) {
                uint32_t b0 = __float_as_uint(W1s[(kb + tig) * 72 + nt * 8 + gid]);
                uint32_t b1 = __float_as_uint(W1s[(kb + tig + 4) * 72 + nt * 8 + gid]);
                mma8(acc[nt], a0, a1, a2, a3, b0, b1);
            }
        }
        __syncthreads();
    }

    const int r0 = row0 + w * 16 + gid;
    const int r1 = r0 + 8;
    const float m0 = (r0 < NNODE) ? 1.f : 0.f;
    const float m1 = (r1 < NNODE) ? 1.f : 0.f;

    float part = 0.f;
#pragma unroll
    for (int nt = 0; nt < 8; nt++) {
        int c = nt * 8 + tig * 2;
        float bb0 = sa_b1[c], bb1 = sa_b1[c + 1];
        float w20 = sa_w2[c], w21 = sa_w2[c + 1];
        part += m0 * (tanhfast(acc[nt][0] + bb0) * w20 + tanhfast(acc[nt][1] + bb1) * w21);
        part += m1 * (tanhfast(acc[nt][2] + bb0) * w20 + tanhfast(acc[nt][3] + bb1) * w21);
    }
#pragma unroll
    for (int o = 16; o > 0; o >>= 1) part += __shfl_xor_sync(0xffffffffu, part, o);
    if (lane == 0) atomicAdd(&s_sum, part);
    __syncthreads();
    if (tid == 0) atomicAdd(&g_wsum[p], s_sum);
}

// ---------------- K6: final weighted sum ----------------
__global__ void k_final(float* __restrict__ out) {
    int i2 = blockIdx.x * blockDim.x + threadIdx.x;
    if (i2 >= NNODE * HD / 2) return;
    float w0 = g_wsum[0] * (1.f / NNODE);
    float w1 = g_wsum[1] * (1.f / NNODE);
    float w2 = g_wsum[2] * (1.f / NNODE);
    float mx = fmaxf(w0, fmaxf(w1, w2));
    float b0 = __expf(w0 - mx), b1 = __expf(w1 - mx), b2 = __expf(w2 - mx);
    float inv = 1.f / (b0 + b1 + b2);
    b0 *= inv; b1 *= inv; b2 *= inv;
    size_t idx = (size_t)i2 * 2;
    float2 z0 = __half22float2(*(const __half2*)&g_zh[idx]);
    float2 z1 = __half22float2(*(const __half2*)&g_zh[(size_t)NNODE * HD + idx]);
    float2 z2 = __half22float2(*(const __half2*)&g_zh[(size_t)2 * NNODE * HD + idx]);
    float2 o;
    o.x = b0 * z0.x + b1 * z1.x + b2 * z2.x;
    o.y = b0 * z0.y + b1 * z1.y + b2 * z2.y;
    *(float2*)&out[idx] = o;
}

// ---------------- launch ----------------
extern "C" void kernel_launch(void* const* d_in, const int* in_sizes, int n_in,
                              void* d_out, int out_size) {
    const float* h    = (const float*)d_in[0];
    const int*   esrc = (const int*)d_in[1];
    const int*   edst = (const int*)d_in[2];
    const float* W    = (const float*)d_in[3];
    const float* al   = (const float*)d_in[4];
    const float* ar   = (const float*)d_in[5];
    const float* bias = (const float*)d_in[6];
    const float* w1   = (const float*)d_in[7];
    const float* b1   = (const float*)d_in[8];
    const float* w2   = (const float*)d_in[9];
    float* out = (float*)d_out;

    static cudaStream_t s2 = nullptr;
    static cudaEvent_t ev_fork = nullptr, ev_csr = nullptr, ev_sem = nullptr;
    static cudaEvent_t ev_p[NP] = {nullptr, nullptr, nullptr};
    if (s2 == nullptr) {
        cudaStreamCreateWithFlags(&s2, cudaStreamNonBlocking);
        cudaEventCreateWithFlags(&ev_fork, cudaEventDisableTiming);
        cudaEventCreateWithFlags(&ev_csr, cudaEventDisableTiming);
        cudaEventCreateWithFlags(&ev_sem, cudaEventDisableTiming);
        for (int p = 0; p < NP; p++)
            cudaEventCreateWithFlags(&ev_p[p], cudaEventDisableTiming);
        cudaFuncSetAttribute(k_gemm, cudaFuncAttributeMaxDynamicSharedMemorySize, GEMM_SMEM);
    }

    // fork: CSR chain on s2, monolithic gemm on main.
    // gemm issued 4th so the ncu capture window profiles it.
    cudaEventRecord(ev_fork, 0);
    cudaStreamWaitEvent(s2, ev_fork, 0);

    k_init<<<(PN + 255) / 256, 256, 0, s2>>>();
    k_count<<<(PE + 255) / 256, 256, 0, s2>>>(edst);
    k_scan_blocks<<<NB, 256, 0, s2>>>();

    k_gemm<<<MBLK, 256, GEMM_SMEM>>>(h, W, al, ar);

    k_scan_bsums<<<1, 512, 0, s2>>>();
    k_scan_final<<<NB, 256, 0, s2>>>();
    k_scatter<<<(PE + 255) / 256, 256, 0, s2>>>(esrc, edst);
    cudaEventRecord(ev_csr, s2);

    // join CSR into main, then per-p aggregate with sem pipelined on s2
    cudaStreamWaitEvent(0, ev_csr, 0);
    for (int p = 0; p < NP; p++) {
        k_p2<<<P2BLK, 256>>>(bias, p);
        cudaEventRecord(ev_p[p], 0);
        cudaStreamWaitEvent(s2, ev_p[p], 0);
        k_sem<<<MBLK, 256, 0, s2>>>(w1, b1, w2, p);
    }
    cudaEventRecord(ev_sem, s2);

    cudaStreamWaitEvent(0, ev_sem, 0);
    k_final<<<(NNODE * HD / 2 + 255) / 256, 256>>>(out);
}

// round 16
// speedup vs baseline: 1.0101x; 1.0101x over previous
#include <cuda_runtime.h>
#include <cuda_fp16.h>
#include <math.h>
#include <stdint.h>

#define NNODE 100000
#define NP 3
#define NE 800000
#define INF 128
#define NH 4
#define HD 128
#define HID 64
#define PN (NP*NNODE)
#define PE (NP*NE)
#define NEG_SLOPE 0.2f

#define SCAN_ITEMS 1024
#define NB ((PN + SCAN_ITEMS - 1) / SCAN_ITEMS)   // 293
#define MBLK ((NNODE + 127) / 128)                // 782
#define P2BLK ((NNODE + 7) / 8)                   // 12500

// gemm dynamic smem: A 128x132 f32 + 2x B 32x136 f32 (double buffer)
#define BCHUNK (32 * 136)
#define GEMM_SMEM ((128 * 132 + 2 * BCHUNK) * 4)  // 102400 B

// ---------------- device scratch (static, no allocations) ----------------
__device__ __align__(16) __half g_feat[(size_t)NP * NNODE * HD];
__device__ __align__(16) __half g_zh[(size_t)NP * NNODE * HD];
__device__ __align__(16) float g_el[PN * NH];
__device__ __align__(16) float g_er[PN * NH];
__device__ int   g_count[PN];
__device__ int   g_cursor[PN];
__device__ int   g_off[PN];
__device__ int   g_bsums[512];
__device__ int   g_esrc[PE];
__device__ float g_wsum[NP];

// ---------------- helpers ----------------
__device__ __forceinline__ float totf32(float x) {
    uint32_t u; asm("cvt.rna.tf32.f32 %0, %1;" : "=r"(u) : "f"(x));
    return __uint_as_float(u);
}
__device__ __forceinline__ float4 totf32_4(float4 v) {
    return make_float4(totf32(v.x), totf32(v.y), totf32(v.z), totf32(v.w));
}
__device__ __forceinline__ void mma8(float* d, uint32_t a0, uint32_t a1,
                                     uint32_t a2, uint32_t a3,
                                     uint32_t b0, uint32_t b1) {
    asm("mma.sync.aligned.m16n8k8.row.col.f32.tf32.tf32.f32 "
        "{%0,%1,%2,%3},{%4,%5,%6,%7},{%8,%9},{%0,%1,%2,%3};"
        : "+f"(d[0]), "+f"(d[1]), "+f"(d[2]), "+f"(d[3])
        : "r"(a0), "r"(a1), "r"(a2), "r"(a3), "r"(b0), "r"(b1));
}
__device__ __forceinline__ float tanhfast(float x) {
    float y; asm("tanh.approx.f32 %0, %1;" : "=f"(y) : "f"(x)); return y;
}
__device__ __forceinline__ float pick4(float4 v, int h) {
    float r = v.x;
    r = (h == 1) ? v.y : r;
    r = (h == 2) ? v.z : r;
    r = (h == 3) ? v.w : r;
    return r;
}
__device__ __forceinline__ float lrelu(float e) {
    return fmaxf(e, NEG_SLOPE * e);
}
__device__ __forceinline__ float4 edge_exp(const float* __restrict__ elbase,
                                           int src, float4 er4) {
    float4 el4 = *(const float4*)&elbase[src * NH];
    return make_float4(__expf(lrelu(el4.x + er4.x)),
                       __expf(lrelu(el4.y + er4.y)),
                       __expf(lrelu(el4.z + er4.z)),
                       __expf(lrelu(el4.w + er4.w)));
}

// ---------------- K0: init ----------------
__global__ void k_init() {
    int i = blockIdx.x * blockDim.x + threadIdx.x;
    if (i < PN) { g_count[i] = 0; g_cursor[i] = 0; }
    if (i < NP) g_wsum[i] = 0.f;
}

// ---------------- K1: feat = h @ W_p, A-resident, double-buffered B (R14) ----------------
// warp grid 4(M) x 2(N): warp owns 32 rows x 64 cols = 2 m-tiles x 8 n-tiles.
__global__ void __launch_bounds__(256, 2) k_gemm(const float* __restrict__ h,
                                                 const float* __restrict__ W,
                                                 const float* __restrict__ attn_l,
                                                 const float* __restrict__ attn_r) {
    extern __shared__ float sm[];
    float* As = sm;                 // 128 x 132 (full K resident)
    float* Bs = sm + 128 * 132;     // 2 x (32 x 136) double buffer

    const int row0 = blockIdx.x * 128;
    const int tid = threadIdx.x;
    const int w = tid >> 5, lane = tid & 31;
    const int gid = lane >> 2, tig = lane & 3;
    const int wm = w & 3;           // M group (32 rows)
    const int wn = w >> 2;          // N half (64 cols)

    for (int i = tid; i < 4096; i += 256) {
        int r = i >> 5, q = i & 31;
        int row = min(row0 + r, NNODE - 1);
        float4 v = *(const float4*)(h + (size_t)row * INF + q * 4);
        *(float4*)&As[r * 132 + q * 4] = totf32_4(v);
    }
    {
        const float* Wc = W;
#pragma unroll
        for (int t = 0; t < 4; t++) {
            int i = tid + t * 256;
            int r = i >> 5, q = i & 31;
            float4 v = *(const float4*)(Wc + (size_t)r * HD + q * 4);
            *(float4*)&Bs[r * 136 + q * 4] = totf32_4(v);
        }
    }
    __syncthreads();

    const int rbase = row0 + wm * 32;
    const int arow[2] = { (wm * 32 + gid) * 132, (wm * 32 + 16 + gid) * 132 };
    const int cbase = wn * 64;

    float acc[2][8][4];
#pragma unroll
    for (int mt = 0; mt < 2; mt++)
#pragma unroll
        for (int nt = 0; nt < 8; nt++) {
            acc[mt][nt][0] = acc[mt][nt][1] = acc[mt][nt][2] = acc[mt][nt][3] = 0.f;
        }

    for (int c = 0; c < 12; c++) {
        const float* curB = Bs + (c & 1) * BCHUNK;

        float4 pf[4];
        if (c < 11) {
            const float* Wc = W + (size_t)((c + 1) >> 2) * INF * HD
                                + (size_t)(((c + 1) & 3) * 32) * HD;
#pragma unroll
            for (int t = 0; t < 4; t++) {
                int i = tid + t * 256;
                int r = i >> 5, q = i & 31;
                pf[t] = *(const float4*)(Wc + (size_t)r * HD + q * 4);
            }
        }

        const int kaBase = (c & 3) * 32;
#pragma unroll
        for (int ks = 0; ks < 4; ks++) {
            int ka = kaBase + ks * 8;
            int kb = ks * 8;
            uint32_t af[2][4];
#pragma unroll
            for (int mt = 0; mt < 2; mt++) {
                af[mt][0] = __float_as_uint(As[arow[mt] + ka + tig]);
                af[mt][1] = __float_as_uint(As[arow[mt] + 8 * 132 + ka + tig]);
                af[mt][2] = __float_as_uint(As[arow[mt] + ka + tig + 4]);
                af[mt][3] = __float_as_uint(As[arow[mt] + 8 * 132 + ka + tig + 4]);
            }
#pragma unroll
            for (int nt = 0; nt < 8; nt++) {
                uint32_t b0 = __float_as_uint(curB[(kb + tig) * 136 + cbase + nt * 8 + gid]);
                uint32_t b1 = __float_as_uint(curB[(kb + tig + 4) * 136 + cbase + nt * 8 + gid]);
                mma8(acc[0][nt], af[0][0], af[0][1], af[0][2], af[0][3], b0, b1);
                mma8(acc[1][nt], af[1][0], af[1][1], af[1][2], af[1][3], b0, b1);
            }
        }

        if (c < 11) {
            float* nxtB = Bs + ((c + 1) & 1) * BCHUNK;
#pragma unroll
            for (int t = 0; t < 4; t++) {
                int i = tid + t * 256;
                int r = i >> 5, q = i & 31;
                *(float4*)&nxtB[r * 136 + q * 4] = totf32_4(pf[t]);
            }
        }
        __syncthreads();

        if ((c & 3) == 3) {
            const int p = c >> 2;
            const float* alp = attn_l + p * HD;
            const float* arp = attn_r + p * HD;
#pragma unroll
            for (int mt = 0; mt < 2; mt++) {
                int r0 = rbase + mt * 16 + gid;
                int r1 = r0 + 8;
                bool ok0 = r0 < NNODE, ok1 = r1 < NNODE;
#pragma unroll
                for (int nt = 0; nt < 8; nt++) {
                    int col = cbase + nt * 8 + tig * 2;
                    if (ok0) *(__half2*)&g_feat[((size_t)p * NNODE + r0) * HD + col] =
                        __floats2half2_rn(acc[mt][nt][0], acc[mt][nt][1]);
                    if (ok1) *(__half2*)&g_feat[((size_t)p * NNODE + r1) * HD + col] =
                        __floats2half2_rn(acc[mt][nt][2], acc[mt][nt][3]);
                }
#pragma unroll
                for (int hl = 0; hl < 2; hl++) {
                    int hd = wn * 2 + hl;
                    float vl0 = 0.f, vl1 = 0.f, vr0 = 0.f, vr1 = 0.f;
#pragma unroll
                    for (int t = 0; t < 4; t++) {
                        int nt = hl * 4 + t;
                        int col = cbase + nt * 8 + tig * 2;
                        float w0 = alp[col], w1 = alp[col + 1];
                        float u0 = arp[col], u1 = arp[col + 1];
                        vl0 += acc[mt][nt][0] * w0 + acc[mt][nt][1] * w1;
                        vl1 += acc[mt][nt][2] * w0 + acc[mt][nt][3] * w1;
                        vr0 += acc[mt][nt][0] * u0 + acc[mt][nt][1] * u1;
                        vr1 += acc[mt][nt][2] * u0 + acc[mt][nt][3] * u1;
                    }
                    vl0 += __shfl_xor_sync(0xffffffffu, vl0, 1); vl0 += __shfl_xor_sync(0xffffffffu, vl0, 2);
                    vl1 += __shfl_xor_sync(0xffffffffu, vl1, 1); vl1 += __shfl_xor_sync(0xffffffffu, vl1, 2);
                    vr0 += __shfl_xor_sync(0xffffffffu, vr0, 1); vr0 += __shfl_xor_sync(0xffffffffu, vr0, 2);
                    vr1 += __shfl_xor_sync(0xffffffffu, vr1, 1); vr1 += __shfl_xor_sync(0xffffffffu, vr1, 2);
                    if (tig == 0) {
                        if (ok0) { g_el[(p * NNODE + r0) * NH + hd] = vl0;
                                   g_er[(p * NNODE + r0) * NH + hd] = vr0; }
                        if (ok1) { g_el[(p * NNODE + r1) * NH + hd] = vl1;
                                   g_er[(p * NNODE + r1) * NH + hd] = vr1; }
                    }
                }
            }
#pragma unroll
            for (int mt = 0; mt < 2; mt++)
#pragma unroll
                for (int nt = 0; nt < 8; nt++) {
                    acc[mt][nt][0] = acc[mt][nt][1] = acc[mt][nt][2] = acc[mt][nt][3] = 0.f;
                }
        }
    }
}

// ---------------- K2: count in-degree (4 edges/thread, int4) ----------------
__global__ void k_count(const int* __restrict__ edge_dst) {
    int i4 = blockIdx.x * blockDim.x + threadIdx.x;
    if (i4 >= PE / 4) return;
    int4 d = ((const int4*)edge_dst)[i4];
    int p = (i4 * 4) / NE;   // NE divisible by 4; all 4 edges same metapath
    int base = p * NNODE;
    atomicAdd(&g_count[base + d.x], 1);
    atomicAdd(&g_count[base + d.y], 1);
    atomicAdd(&g_count[base + d.z], 1);
    atomicAdd(&g_count[base + d.w], 1);
}

// ---------------- scan (3 kernels) ----------------
__global__ void k_scan_blocks() {
    __shared__ int s[256];
    int base = blockIdx.x * SCAN_ITEMS;
    int t = threadIdx.x;
    int v = 0;
#pragma unroll
    for (int i = 0; i < 4; i++) {
        int idx = base + t * 4 + i;
        if (idx < PN) v += g_count[idx];
    }
    s[t] = v; __syncthreads();
    for (int o = 128; o > 0; o >>= 1) {
        if (t < o) s[t] += s[t + o];
        __syncthreads();
    }
    if (t == 0) g_bsums[blockIdx.x] = s[0];
}

__global__ void k_scan_bsums() {
    __shared__ int s[512];
    int t = threadIdx.x;
    int v = (t < NB) ? g_bsums[t] : 0;
    s[t] = v; __syncthreads();
    for (int o = 1; o < 512; o <<= 1) {
        int x = (t >= o) ? s[t - o] : 0;
        __syncthreads();
        s[t] += x;
        __syncthreads();
    }
    if (t < NB) g_bsums[t] = s[t] - v;  // exclusive
}

__global__ void k_scan_final() {
    __shared__ int s[256];
    int base = blockIdx.x * SCAN_ITEMS;
    int t = threadIdx.x;
    int loc[4]; int sum = 0;
#pragma unroll
    for (int i = 0; i < 4; i++) {
        int idx = base + t * 4 + i;
        loc[i] = (idx < PN) ? g_count[idx] : 0;
        sum += loc[i];
    }
    s[t] = sum; __syncthreads();
    for (int o = 1; o < 256; o <<= 1) {
        int x = (t >= o) ? s[t - o] : 0;
        __syncthreads();
        s[t] += x;
        __syncthreads();
    }
    int ex = s[t] - sum + g_bsums[blockIdx.x];
#pragma unroll
    for (int i = 0; i < 4; i++) {
        int idx = base + t * 4 + i;
        if (idx < PN) { g_off[idx] = ex; ex += loc[i]; }
    }
}

// ---------------- K3: scatter src by dst (4 edges/thread, int4) ----------------
__global__ void k_scatter(const int* __restrict__ edge_src,
                          const int* __restrict__ edge_dst) {
    int i4 = blockIdx.x * blockDim.x + threadIdx.x;
    if (i4 >= PE / 4) return;
    int4 d = ((const int4*)edge_dst)[i4];
    int4 s = ((const int4*)edge_src)[i4];
    int p = (i4 * 4) / NE;
    int base = p * NNODE;
    int seg, pos;
    seg = base + d.x; pos = atomicAdd(&g_cursor[seg], 1); g_esrc[g_off[seg] + pos] = s.x;
    seg = base + d.y; pos = atomicAdd(&g_cursor[seg], 1); g_esrc[g_off[seg] + pos] = s.y;
    seg = base + d.z; pos = atomicAdd(&g_cursor[seg], 1); g_esrc[g_off[seg] + pos] = s.z;
    seg = base + d.w; pos = atomicAdd(&g_cursor[seg], 1); g_esrc[g_off[seg] + pos] = s.w;
}

// ---------------- K4: fused GAT softmax + aggregate (one metapath) ----------------
__global__ void __launch_bounds__(256) k_p2(const float* __restrict__ bias, int p) {
    __shared__ float sex[8 * 128];   // per-warp 32 x float4 ex table
    int node = (blockIdx.x * blockDim.x + threadIdx.x) >> 5;
    if (node >= NNODE) return;
    const int wid = (threadIdx.x >> 5);
    const int lane = threadIdx.x & 31;
    const int seg = p * NNODE + node;
    const int start = g_off[seg];
    const int cnt = g_count[seg];
    const int hd = lane >> 3;
    float* myex = &sex[wid * 128];
    const float* elbase = g_el + (size_t)p * NNODE * NH;
    const __half* fb = g_feat + (size_t)p * NNODE * HD;
    const float4 er4 = *(const float4*)&g_er[seg * NH];

    float4 a = *(const float4*)&bias[p * HD + lane * 4];

    if (cnt > 0 && cnt <= 32) {
        int src = 0;
        float4 ex = make_float4(0.f, 0.f, 0.f, 0.f);
        if (lane < cnt) {
            src = g_esrc[start + lane];
            ex = edge_exp(elbase, src, er4);
        }
        *(float4*)&myex[lane * 4] = ex;
        __syncwarp();
        float4 s = ex;
#pragma unroll
        for (int o = 16; o > 0; o >>= 1) {
            s.x += __shfl_xor_sync(0xffffffffu, s.x, o);
            s.y += __shfl_xor_sync(0xffffffffu, s.y, o);
            s.z += __shfl_xor_sync(0xffffffffu, s.z, o);
            s.w += __shfl_xor_sync(0xffffffffu, s.w, o);
        }
        float rs = 1.f / fmaxf(pick4(s, hd), 1e-9f);
#pragma unroll 4
        for (int j = 0; j < cnt; j++) {
            int sj = __shfl_sync(0xffffffffu, src, j);
            float wgt = myex[j * 4 + hd] * rs;
            uint2 fv = *(const uint2*)&fb[(size_t)sj * HD + lane * 4];
            float2 g01 = __half22float2(*(__half2*)&fv.x);
            float2 g23 = __half22float2(*(__half2*)&fv.y);
            a.x += wgt * g01.x; a.y += wgt * g01.y;
            a.z += wgt * g23.x; a.w += wgt * g23.y;
        }
    } else if (cnt > 32) {
        float4 s = make_float4(0.f, 0.f, 0.f, 0.f);
        for (int c0 = 0; c0 < cnt; c0 += 32) {
            if (c0 + lane < cnt) {
                int src = g_esrc[start + c0 + lane];
                float4 ex = edge_exp(elbase, src, er4);
                s.x += ex.x; s.y += ex.y; s.z += ex.z; s.w += ex.w;
            }
        }
#pragma unroll
        for (int o = 16; o > 0; o >>= 1) {
            s.x += __shfl_xor_sync(0xffffffffu, s.x, o);
            s.y += __shfl_xor_sync(0xffffffffu, s.y, o);
            s.z += __shfl_xor_sync(0xffffffffu, s.z, o);
            s.w += __shfl_xor_sync(0xffffffffu, s.w, o);
        }
        float rs = 1.f / fmaxf(pick4(s, hd), 1e-9f);
        for (int c0 = 0; c0 < cnt; c0 += 32) {
            int src = 0;
            float4 ex = make_float4(0.f, 0.f, 0.f, 0.f);
            if (c0 + lane < cnt) {
                src = g_esrc[start + c0 + lane];
                ex = edge_exp(elbase, src, er4);
            }
            *(float4*)&myex[lane * 4] = ex;
            __syncwarp();
            int lim = min(32, cnt - c0);
            for (int j = 0; j < lim; j++) {
                int sj = __shfl_sync(0xffffffffu, src, j);
                float wgt = myex[j * 4 + hd] * rs;
                uint2 fv = *(const uint2*)&fb[(size_t)sj * HD + lane * 4];
                float2 g01 = __half22float2(*(__half2*)&fv.x);
                float2 g23 = __half22float2(*(__half2*)&fv.y);
                a.x += wgt * g01.x; a.y += wgt * g01.y;
                a.z += wgt * g23.x; a.w += wgt * g23.y;
            }
            __syncwarp();
        }
    }
    __half2 z01 = __floats2half2_rn(a.x, a.y);
    __half2 z23 = __floats2half2_rn(a.z, a.w);
    uint2 zv;
    zv.x = *(uint32_t*)&z01;
    zv.y = *(uint32_t*)&z23;
    *(uint2*)&g_zh[(size_t)seg * HD + lane * 4] = zv;
}

// ---------------- K5: semantic score (one metapath) ----------------
__global__ void __launch_bounds__(256) k_sem(const float* __restrict__ sa_w1,
                                             const float* __restrict__ sa_b1,
                                             const float* __restrict__ sa_w2,
                                             int p) {
    __shared__ float Zs[128 * 36];
    __shared__ float W1s[32 * 72];
    __shared__ float s_sum;

    const int row0 = blockIdx.x * 128;
    const int tid = threadIdx.x;
    const int w = tid >> 5, lane = tid & 31;
    const int gid = lane >> 2, tig = lane & 3;
    if (tid == 0) s_sum = 0.f;

    float acc[8][4];
#pragma unroll
    for (int t = 0; t < 8; t++) { acc[t][0] = acc[t][1] = acc[t][2] = acc[t][3] = 0.f; }

    const __half* zb = g_zh + (size_t)p * NNODE * HD;
    for (int kc = 0; kc < 4; kc++) {
        for (int i = tid; i < 1024; i += 256) {
            int r = i >> 3, q = i & 7;
            float4 o = make_float4(0.f, 0.f, 0.f, 0.f);
            if (row0 + r < NNODE) {
                uint2 hv = *(const uint2*)(zb + (size_t)(row0 + r) * HD + kc * 32 + q * 4);
                float2 f01 = __half22float2(*(__half2*)&hv.x);
                float2 f23 = __half22float2(*(__half2*)&hv.y);
                o = make_float4(totf32(f01.x), totf32(f01.y), totf32(f23.x), totf32(f23.y));
            }
            *(float4*)&Zs[r * 36 + q * 4] = o;
        }
        for (int i = tid; i < 512; i += 256) {
            int r = i >> 4, q = i & 15;
            float4 v = *(const float4*)(sa_w1 + (size_t)(kc * 32 + r) * HID + q * 4);
            *(float4*)&W1s[r * 72 + q * 4] = totf32_4(v);
        }
        __syncthreads();

#pragma unroll
        for (int ks = 0; ks < 4; ks++) {
            int kb = ks * 8;
            uint32_t a0 = __float_as_uint(Zs[(w * 16 + gid) * 36 + kb + tig]);
            uint32_t a1 = __float_as_uint(Zs[(w * 16 + gid + 8) * 36 + kb + tig]);
            uint32_t a2 = __float_as_uint(Zs[(w * 16 + gid) * 36 + kb + tig + 4]);
            uint32_t a3 = __float_as_uint(Zs[(w * 16 + gid + 8) * 36 + kb + tig + 4]);
#pragma unroll
            for (int nt = 0; nt < 8; nt++) {
                uint32_t b0 = __float_as_uint(W1s[(kb + tig) * 72 + nt * 8 + gid]);
                uint32_t b1 = __float_as_uint(W1s[(kb + tig + 4) * 72 + nt * 8 + gid]);
                mma8(acc[nt], a0, a1, a2, a3, b0, b1);
            }
        }
        __syncthreads();
    }

    const int r0 = row0 + w * 16 + gid;
    const int r1 = r0 + 8;
    const float m0 = (r0 < NNODE) ? 1.f : 0.f;
    const float m1 = (r1 < NNODE) ? 1.f : 0.f;

    float part = 0.f;
#pragma unroll
    for (int nt = 0; nt < 8; nt++) {
        int c = nt * 8 + tig * 2;
        float bb0 = sa_b1[c], bb1 = sa_b1[c + 1];
        float w20 = sa_w2[c], w21 = sa_w2[c + 1];
        part += m0 * (tanhfast(acc[nt][0] + bb0) * w20 + tanhfast(acc[nt][1] + bb1) * w21);
        part += m1 * (tanhfast(acc[nt][2] + bb0) * w20 + tanhfast(acc[nt][3] + bb1) * w21);
    }
#pragma unroll
    for (int o = 16; o > 0; o >>= 1) part += __shfl_xor_sync(0xffffffffu, part, o);
    if (lane == 0) atomicAdd(&s_sum, part);
    __syncthreads();
    if (tid == 0) atomicAdd(&g_wsum[p], s_sum);
}

// ---------------- K6: final weighted sum ----------------
__global__ void k_final(float* __restrict__ out) {
    int i2 = blockIdx.x * blockDim.x + threadIdx.x;
    if (i2 >= NNODE * HD / 2) return;
    float w0 = g_wsum[0] * (1.f / NNODE);
    float w1 = g_wsum[1] * (1.f / NNODE);
    float w2 = g_wsum[2] * (1.f / NNODE);
    float mx = fmaxf(w0, fmaxf(w1, w2));
    float b0 = __expf(w0 - mx), b1 = __expf(w1 - mx), b2 = __expf(w2 - mx);
    float inv = 1.f / (b0 + b1 + b2);
    b0 *= inv; b1 *= inv; b2 *= inv;
    size_t idx = (size_t)i2 * 2;
    float2 z0 = __half22float2(*(const __half2*)&g_zh[idx]);
    float2 z1 = __half22float2(*(const __half2*)&g_zh[(size_t)NNODE * HD + idx]);
    float2 z2 = __half22float2(*(const __half2*)&g_zh[(size_t)2 * NNODE * HD + idx]);
    float2 o;
    o.x = b0 * z0.x + b1 * z1.x + b2 * z2.x;
    o.y = b0 * z0.y + b1 * z1.y + b2 * z2.y;
    *(float2*)&out[idx] = o;
}

// ---------------- launch ----------------
extern "C" void kernel_launch(void* const* d_in, const int* in_sizes, int n_in,
                              void* d_out, int out_size) {
    const float* h    = (const float*)d_in[0];
    const int*   esrc = (const int*)d_in[1];
    const int*   edst = (const int*)d_in[2];
    const float* W    = (const float*)d_in[3];
    const float* al   = (const float*)d_in[4];
    const float* ar   = (const float*)d_in[5];
    const float* bias = (const float*)d_in[6];
    const float* w1   = (const float*)d_in[7];
    const float* b1   = (const float*)d_in[8];
    const float* w2   = (const float*)d_in[9];
    float* out = (float*)d_out;

    static cudaStream_t s2 = nullptr;
    static cudaEvent_t ev_fork = nullptr, ev_csr = nullptr, ev_sem = nullptr;
    static cudaEvent_t ev_p[NP] = {nullptr, nullptr, nullptr};
    if (s2 == nullptr) {
        cudaStreamCreateWithFlags(&s2, cudaStreamNonBlocking);
        cudaEventCreateWithFlags(&ev_fork, cudaEventDisableTiming);
        cudaEventCreateWithFlags(&ev_csr, cudaEventDisableTiming);
        cudaEventCreateWithFlags(&ev_sem, cudaEventDisableTiming);
        for (int p = 0; p < NP; p++)
            cudaEventCreateWithFlags(&ev_p[p], cudaEventDisableTiming);
        cudaFuncSetAttribute(k_gemm, cudaFuncAttributeMaxDynamicSharedMemorySize, GEMM_SMEM);
    }

    // fork: CSR chain on s2, monolithic gemm on main.
    cudaEventRecord(ev_fork, 0);
    cudaStreamWaitEvent(s2, ev_fork, 0);

    k_init<<<(PN + 255) / 256, 256, 0, s2>>>();
    k_count<<<(PE / 4 + 255) / 256, 256, 0, s2>>>(edst);
    k_scan_blocks<<<NB, 256, 0, s2>>>();

    k_gemm<<<MBLK, 256, GEMM_SMEM>>>(h, W, al, ar);

    k_scan_bsums<<<1, 512, 0, s2>>>();
    k_scan_final<<<NB, 256, 0, s2>>>();
    k_scatter<<<(PE / 4 + 255) / 256, 256, 0, s2>>>(esrc, edst);
    cudaEventRecord(ev_csr, s2);

    // join CSR into main, then per-p aggregate with sem pipelined on s2
    cudaStreamWaitEvent(0, ev_csr, 0);
    for (int p = 0; p < NP; p++) {
        k_p2<<<P2BLK, 256>>>(bias, p);
        cudaEventRecord(ev_p[p], 0);
        cudaStreamWaitEvent(s2, ev_p[p], 0);
        k_sem<<<MBLK, 256, 0, s2>>>(w1, b1, w2, p);
    }
    cudaEventRecord(ev_sem, s2);

    cudaStreamWaitEvent(0, ev_sem, 0);
    k_final<<<(NNODE * HD / 2 + 255) / 256, 256>>>(out);
}

// round 17
// speedup vs baseline: 1.1190x; 1.1078x over previous
#include <cuda_runtime.h>
#include <cuda_fp16.h>
#include <math.h>
#include <stdint.h>

#define NNODE 100000
#define NP 3
#define NE 800000
#define INF 128
#define NH 4
#define HD 128
#define HID 64
#define PN (NP*NNODE)
#define PE (NP*NE)
#define NEG_SLOPE 0.2f

#define SCAN_ITEMS 1024
#define NB ((PN + SCAN_ITEMS - 1) / SCAN_ITEMS)   // 293
#define MBLK ((NNODE + 127) / 128)                // 782
#define P2BLK ((NNODE + 7) / 8)                   // 12500

// gemm dynamic smem: A 128x132 f32 + 2x B 32x136 f32 (double buffer)
#define BCHUNK (32 * 136)
#define GEMM_SMEM ((128 * 132 + 2 * BCHUNK) * 4)  // 102400 B

// ---------------- device scratch (static, no allocations) ----------------
__device__ __align__(16) __half g_feat[(size_t)NP * NNODE * HD];
__device__ __align__(16) __half g_zh[(size_t)NP * NNODE * HD];
__device__ __align__(16) float g_el[PN * NH];
__device__ __align__(16) float g_er[PN * NH];
__device__ int   g_count[PN];
__device__ int   g_cursor[PN];
__device__ int   g_off[PN];
__device__ int   g_bsums[512];
__device__ int   g_esrc[PE];
__device__ float g_wsum[NP];

// ---------------- helpers ----------------
__device__ __forceinline__ float totf32(float x) {
    uint32_t u; asm("cvt.rna.tf32.f32 %0, %1;" : "=r"(u) : "f"(x));
    return __uint_as_float(u);
}
__device__ __forceinline__ float4 totf32_4(float4 v) {
    return make_float4(totf32(v.x), totf32(v.y), totf32(v.z), totf32(v.w));
}
__device__ __forceinline__ void mma8(float* d, uint32_t a0, uint32_t a1,
                                     uint32_t a2, uint32_t a3,
                                     uint32_t b0, uint32_t b1) {
    asm("mma.sync.aligned.m16n8k8.row.col.f32.tf32.tf32.f32 "
        "{%0,%1,%2,%3},{%4,%5,%6,%7},{%8,%9},{%0,%1,%2,%3};"
        : "+f"(d[0]), "+f"(d[1]), "+f"(d[2]), "+f"(d[3])
        : "r"(a0), "r"(a1), "r"(a2), "r"(a3), "r"(b0), "r"(b1));
}
__device__ __forceinline__ float tanhfast(float x) {
    float y; asm("tanh.approx.f32 %0, %1;" : "=f"(y) : "f"(x)); return y;
}
__device__ __forceinline__ float pick4(float4 v, int h) {
    float r = v.x;
    r = (h == 1) ? v.y : r;
    r = (h == 2) ? v.z : r;
    r = (h == 3) ? v.w : r;
    return r;
}
__device__ __forceinline__ float lrelu(float e) {
    return fmaxf(e, NEG_SLOPE * e);
}
__device__ __forceinline__ float4 edge_exp(const float* __restrict__ elbase,
                                           int src, float4 er4) {
    float4 el4 = *(const float4*)&elbase[src * NH];
    return make_float4(__expf(lrelu(el4.x + er4.x)),
                       __expf(lrelu(el4.y + er4.y)),
                       __expf(lrelu(el4.z + er4.z)),
                       __expf(lrelu(el4.w + er4.w)));
}

// ---------------- K0: init ----------------
__global__ void k_init() {
    int i = blockIdx.x * blockDim.x + threadIdx.x;
    if (i < PN) { g_count[i] = 0; g_cursor[i] = 0; }
    if (i < NP) g_wsum[i] = 0.f;
}

// ---------------- K1: feat = h @ W_p, A-resident, double-buffered B ----------------
// warp grid 4(M) x 2(N): warp owns 32 rows x 64 cols = 2 m-tiles x 8 n-tiles.
__global__ void __launch_bounds__(256, 2) k_gemm(const float* __restrict__ h,
                                                 const float* __restrict__ W,
                                                 const float* __restrict__ attn_l,
                                                 const float* __restrict__ attn_r) {
    extern __shared__ float sm[];
    float* As = sm;                 // 128 x 132 (full K resident)
    float* Bs = sm + 128 * 132;     // 2 x (32 x 136) double buffer

    const int row0 = blockIdx.x * 128;
    const int tid = threadIdx.x;
    const int w = tid >> 5, lane = tid & 31;
    const int gid = lane >> 2, tig = lane & 3;
    const int wm = w & 3;           // M group (32 rows)
    const int wn = w >> 2;          // N half (64 cols)

    for (int i = tid; i < 4096; i += 256) {
        int r = i >> 5, q = i & 31;
        int row = min(row0 + r, NNODE - 1);
        float4 v = *(const float4*)(h + (size_t)row * INF + q * 4);
        *(float4*)&As[r * 132 + q * 4] = totf32_4(v);
    }
    {
        const float* Wc = W;
#pragma unroll
        for (int t = 0; t < 4; t++) {
            int i = tid + t * 256;
            int r = i >> 5, q = i & 31;
            float4 v = *(const float4*)(Wc + (size_t)r * HD + q * 4);
            *(float4*)&Bs[r * 136 + q * 4] = totf32_4(v);
        }
    }
    __syncthreads();

    const int rbase = row0 + wm * 32;
    const int arow[2] = { (wm * 32 + gid) * 132, (wm * 32 + 16 + gid) * 132 };
    const int cbase = wn * 64;

    float acc[2][8][4];
#pragma unroll
    for (int mt = 0; mt < 2; mt++)
#pragma unroll
        for (int nt = 0; nt < 8; nt++) {
            acc[mt][nt][0] = acc[mt][nt][1] = acc[mt][nt][2] = acc[mt][nt][3] = 0.f;
        }

    for (int c = 0; c < 12; c++) {
        const float* curB = Bs + (c & 1) * BCHUNK;

        float4 pf[4];
        if (c < 11) {
            const float* Wc = W + (size_t)((c + 1) >> 2) * INF * HD
                                + (size_t)(((c + 1) & 3) * 32) * HD;
#pragma unroll
            for (int t = 0; t < 4; t++) {
                int i = tid + t * 256;
                int r = i >> 5, q = i & 31;
                pf[t] = *(const float4*)(Wc + (size_t)r * HD + q * 4);
            }
        }

        const int kaBase = (c & 3) * 32;
#pragma unroll
        for (int ks = 0; ks < 4; ks++) {
            int ka = kaBase + ks * 8;
            int kb = ks * 8;
            uint32_t af[2][4];
#pragma unroll
            for (int mt = 0; mt < 2; mt++) {
                af[mt][0] = __float_as_uint(As[arow[mt] + ka + tig]);
                af[mt][1] = __float_as_uint(As[arow[mt] + 8 * 132 + ka + tig]);
                af[mt][2] = __float_as_uint(As[arow[mt] + ka + tig + 4]);
                af[mt][3] = __float_as_uint(As[arow[mt] + 8 * 132 + ka + tig + 4]);
            }
#pragma unroll
            for (int nt = 0; nt < 8; nt++) {
                uint32_t b0 = __float_as_uint(curB[(kb + tig) * 136 + cbase + nt * 8 + gid]);
                uint32_t b1 = __float_as_uint(curB[(kb + tig + 4) * 136 + cbase + nt * 8 + gid]);
                mma8(acc[0][nt], af[0][0], af[0][1], af[0][2], af[0][3], b0, b1);
                mma8(acc[1][nt], af[1][0], af[1][1], af[1][2], af[1][3], b0, b1);
            }
        }

        if (c < 11) {
            float* nxtB = Bs + ((c + 1) & 1) * BCHUNK;
#pragma unroll
            for (int t = 0; t < 4; t++) {
                int i = tid + t * 256;
                int r = i >> 5, q = i & 31;
                *(float4*)&nxtB[r * 136 + q * 4] = totf32_4(pf[t]);
            }
        }
        __syncthreads();

        if ((c & 3) == 3) {
            const int p = c >> 2;
            const float* alp = attn_l + p * HD;
            const float* arp = attn_r + p * HD;
#pragma unroll
            for (int mt = 0; mt < 2; mt++) {
                int r0 = rbase + mt * 16 + gid;
                int r1 = r0 + 8;
                bool ok0 = r0 < NNODE, ok1 = r1 < NNODE;
#pragma unroll
                for (int nt = 0; nt < 8; nt++) {
                    int col = cbase + nt * 8 + tig * 2;
                    if (ok0) *(__half2*)&g_feat[((size_t)p * NNODE + r0) * HD + col] =
                        __floats2half2_rn(acc[mt][nt][0], acc[mt][nt][1]);
                    if (ok1) *(__half2*)&g_feat[((size_t)p * NNODE + r1) * HD + col] =
                        __floats2half2_rn(acc[mt][nt][2], acc[mt][nt][3]);
                }
#pragma unroll
                for (int hl = 0; hl < 2; hl++) {
                    int hd = wn * 2 + hl;
                    float vl0 = 0.f, vl1 = 0.f, vr0 = 0.f, vr1 = 0.f;
#pragma unroll
                    for (int t = 0; t < 4; t++) {
                        int nt = hl * 4 + t;
                        int col = cbase + nt * 8 + tig * 2;
                        float w0 = alp[col], w1 = alp[col + 1];
                        float u0 = arp[col], u1 = arp[col + 1];
                        vl0 += acc[mt][nt][0] * w0 + acc[mt][nt][1] * w1;
                        vl1 += acc[mt][nt][2] * w0 + acc[mt][nt][3] * w1;
                        vr0 += acc[mt][nt][0] * u0 + acc[mt][nt][1] * u1;
                        vr1 += acc[mt][nt][2] * u0 + acc[mt][nt][3] * u1;
                    }
                    vl0 += __shfl_xor_sync(0xffffffffu, vl0, 1); vl0 += __shfl_xor_sync(0xffffffffu, vl0, 2);
                    vl1 += __shfl_xor_sync(0xffffffffu, vl1, 1); vl1 += __shfl_xor_sync(0xffffffffu, vl1, 2);
                    vr0 += __shfl_xor_sync(0xffffffffu, vr0, 1); vr0 += __shfl_xor_sync(0xffffffffu, vr0, 2);
                    vr1 += __shfl_xor_sync(0xffffffffu, vr1, 1); vr1 += __shfl_xor_sync(0xffffffffu, vr1, 2);
                    if (tig == 0) {
                        if (ok0) { g_el[(p * NNODE + r0) * NH + hd] = vl0;
                                   g_er[(p * NNODE + r0) * NH + hd] = vr0; }
                        if (ok1) { g_el[(p * NNODE + r1) * NH + hd] = vl1;
                                   g_er[(p * NNODE + r1) * NH + hd] = vr1; }
                    }
                }
            }
#pragma unroll
            for (int mt = 0; mt < 2; mt++)
#pragma unroll
                for (int nt = 0; nt < 8; nt++) {
                    acc[mt][nt][0] = acc[mt][nt][1] = acc[mt][nt][2] = acc[mt][nt][3] = 0.f;
                }
        }
    }
}

// ---------------- K2: count in-degree (one edge per thread) ----------------
__global__ void k_count(const int* __restrict__ edge_dst) {
    int i = blockIdx.x * blockDim.x + threadIdx.x;
    if (i >= PE) return;
    int p = i / NE;
    atomicAdd(&g_count[p * NNODE + edge_dst[i]], 1);
}

// ---------------- scan (3 kernels) ----------------
__global__ void k_scan_blocks() {
    __shared__ int s[256];
    int base = blockIdx.x * SCAN_ITEMS;
    int t = threadIdx.x;
    int v = 0;
#pragma unroll
    for (int i = 0; i < 4; i++) {
        int idx = base + t * 4 + i;
        if (idx < PN) v += g_count[idx];
    }
    s[t] = v; __syncthreads();
    for (int o = 128; o > 0; o >>= 1) {
        if (t < o) s[t] += s[t + o];
        __syncthreads();
    }
    if (t == 0) g_bsums[blockIdx.x] = s[0];
}

__global__ void k_scan_bsums() {
    __shared__ int s[512];
    int t = threadIdx.x;
    int v = (t < NB) ? g_bsums[t] : 0;
    s[t] = v; __syncthreads();
    for (int o = 1; o < 512; o <<= 1) {
        int x = (t >= o) ? s[t - o] : 0;
        __syncthreads();
        s[t] += x;
        __syncthreads();
    }
    if (t < NB) g_bsums[t] = s[t] - v;  // exclusive
}

__global__ void k_scan_final() {
    __shared__ int s[256];
    int base = blockIdx.x * SCAN_ITEMS;
    int t = threadIdx.x;
    int loc[4]; int sum = 0;
#pragma unroll
    for (int i = 0; i < 4; i++) {
        int idx = base + t * 4 + i;
        loc[i] = (idx < PN) ? g_count[idx] : 0;
        sum += loc[i];
    }
    s[t] = sum; __syncthreads();
    for (int o = 1; o < 256; o <<= 1) {
        int x = (t >= o) ? s[t - o] : 0;
        __syncthreads();
        s[t] += x;
        __syncthreads();
    }
    int ex = s[t] - sum + g_bsums[blockIdx.x];
#pragma unroll
    for (int i = 0; i < 4; i++) {
        int idx = base + t * 4 + i;
        if (idx < PN) { g_off[idx] = ex; ex += loc[i]; }
    }
}

// ---------------- K3: scatter src by dst (one edge per thread) ----------------
__global__ void k_scatter(const int* __restrict__ edge_src,
                          const int* __restrict__ edge_dst) {
    int i = blockIdx.x * blockDim.x + threadIdx.x;
    if (i >= PE) return;
    int p = i / NE;
    int seg = p * NNODE + edge_dst[i];
    int pos = atomicAdd(&g_cursor[seg], 1);
    g_esrc[g_off[seg] + pos] = edge_src[i];
}

// ---------------- K4: fused GAT softmax + aggregate (one metapath) ----------------
__global__ void __launch_bounds__(256) k_p2(const float* __restrict__ bias, int p) {
    __shared__ float sex[8 * 128];   // per-warp 32 x float4 ex table
    int node = (blockIdx.x * blockDim.x + threadIdx.x) >> 5;
    if (node >= NNODE) return;
    const int wid = (threadIdx.x >> 5);
    const int lane = threadIdx.x & 31;
    const int seg = p * NNODE + node;
    const int start = g_off[seg];
    const int cnt = g_count[seg];
    const int hd = lane >> 3;
    float* myex = &sex[wid * 128];
    const float* elbase = g_el + (size_t)p * NNODE * NH;
    const __half* fb = g_feat + (size_t)p * NNODE * HD;
    const float4 er4 = *(const float4*)&g_er[seg * NH];

    float4 a = *(const float4*)&bias[p * HD + lane * 4];

    if (cnt > 0 && cnt <= 32) {
        int src = 0;
        float4 ex = make_float4(0.f, 0.f, 0.f, 0.f);
        if (lane < cnt) {
            src = g_esrc[start + lane];
            ex = edge_exp(elbase, src, er4);
        }
        *(float4*)&myex[lane * 4] = ex;
        __syncwarp();
        float4 s = ex;
#pragma unroll
        for (int o = 16; o > 0; o >>= 1) {
            s.x += __shfl_xor_sync(0xffffffffu, s.x, o);
            s.y += __shfl_xor_sync(0xffffffffu, s.y, o);
            s.z += __shfl_xor_sync(0xffffffffu, s.z, o);
            s.w += __shfl_xor_sync(0xffffffffu, s.w, o);
        }
        float rs = 1.f / fmaxf(pick4(s, hd), 1e-9f);
#pragma unroll 4
        for (int j = 0; j < cnt; j++) {
            int sj = __shfl_sync(0xffffffffu, src, j);
            float wgt = myex[j * 4 + hd] * rs;
            uint2 fv = *(const uint2*)&fb[(size_t)sj * HD + lane * 4];
            float2 g01 = __half22float2(*(__half2*)&fv.x);
            float2 g23 = __half22float2(*(__half2*)&fv.y);
            a.x += wgt * g01.x; a.y += wgt * g01.y;
            a.z += wgt * g23.x; a.w += wgt * g23.y;
        }
    } else if (cnt > 32) {
        float4 s = make_float4(0.f, 0.f, 0.f, 0.f);
        for (int c0 = 0; c0 < cnt; c0 += 32) {
            if (c0 + lane < cnt) {
                int src = g_esrc[start + c0 + lane];
                float4 ex = edge_exp(elbase, src, er4);
                s.x += ex.x; s.y += ex.y; s.z += ex.z; s.w += ex.w;
            }
        }
#pragma unroll
        for (int o = 16; o > 0; o >>= 1) {
            s.x += __shfl_xor_sync(0xffffffffu, s.x, o);
            s.y += __shfl_xor_sync(0xffffffffu, s.y, o);
            s.z += __shfl_xor_sync(0xffffffffu, s.z, o);
            s.w += __shfl_xor_sync(0xffffffffu, s.w, o);
        }
        float rs = 1.f / fmaxf(pick4(s, hd), 1e-9f);
        for (int c0 = 0; c0 < cnt; c0 += 32) {
            int src = 0;
            float4 ex = make_float4(0.f, 0.f, 0.f, 0.f);
            if (c0 + lane < cnt) {
                src = g_esrc[start + c0 + lane];
                ex = edge_exp(elbase, src, er4);
            }
            *(float4*)&myex[lane * 4] = ex;
            __syncwarp();
            int lim = min(32, cnt - c0);
            for (int j = 0; j < lim; j++) {
                int sj = __shfl_sync(0xffffffffu, src, j);
                float wgt = myex[j * 4 + hd] * rs;
                uint2 fv = *(const uint2*)&fb[(size_t)sj * HD + lane * 4];
                float2 g01 = __half22float2(*(__half2*)&fv.x);
                float2 g23 = __half22float2(*(__half2*)&fv.y);
                a.x += wgt * g01.x; a.y += wgt * g01.y;
                a.z += wgt * g23.x; a.w += wgt * g23.y;
            }
            __syncwarp();
        }
    }
    __half2 z01 = __floats2half2_rn(a.x, a.y);
    __half2 z23 = __floats2half2_rn(a.z, a.w);
    uint2 zv;
    zv.x = *(uint32_t*)&z01;
    zv.y = *(uint32_t*)&z23;
    *(uint2*)&g_zh[(size_t)seg * HD + lane * 4] = zv;
}

// ---------------- K5: semantic score (one metapath) ----------------
__global__ void __launch_bounds__(256) k_sem(const float* __restrict__ sa_w1,
                                             const float* __restrict__ sa_b1,
                                             const float* __restrict__ sa_w2,
                                             int p) {
    __shared__ float Zs[128 * 36];
    __shared__ float W1s[32 * 72];
    __shared__ float s_sum;

    const int row0 = blockIdx.x * 128;
    const int tid = threadIdx.x;
    const int w = tid >> 5, lane = tid & 31;
    const int gid = lane >> 2, tig = lane & 3;
    if (tid == 0) s_sum = 0.f;

    float acc[8][4];
#pragma unroll
    for (int t = 0; t < 8; t++) { acc[t][0] = acc[t][1] = acc[t][2] = acc[t][3] = 0.f; }

    const __half* zb = g_zh + (size_t)p * NNODE * HD;
    for (int kc = 0; kc < 4; kc++) {
        for (int i = tid; i < 1024; i += 256) {
            int r = i >> 3, q = i & 7;
            float4 o = make_float4(0.f, 0.f, 0.f, 0.f);
            if (row0 + r < NNODE) {
                uint2 hv = *(const uint2*)(zb + (size_t)(row0 + r) * HD + kc * 32 + q * 4);
                float2 f01 = __half22float2(*(__half2*)&hv.x);
                float2 f23 = __half22float2(*(__half2*)&hv.y);
                o = make_float4(totf32(f01.x), totf32(f01.y), totf32(f23.x), totf32(f23.y));
            }
            *(float4*)&Zs[r * 36 + q * 4] = o;
        }
        for (int i = tid; i < 512; i += 256) {
            int r = i >> 4, q = i & 15;
            float4 v = *(const float4*)(sa_w1 + (size_t)(kc * 32 + r) * HID + q * 4);
            *(float4*)&W1s[r * 72 + q * 4] = totf32_4(v);
        }
        __syncthreads();

#pragma unroll
        for (int ks = 0; ks < 4; ks++) {
            int kb = ks * 8;
            uint32_t a0 = __float_as_uint(Zs[(w * 16 + gid) * 36 + kb + tig]);
            uint32_t a1 = __float_as_uint(Zs[(w * 16 + gid + 8) * 36 + kb + tig]);
            uint32_t a2 = __float_as_uint(Zs[(w * 16 + gid) * 36 + kb + tig + 4]);
            uint32_t a3 = __float_as_uint(Zs[(w * 16 + gid + 8) * 36 + kb + tig + 4]);
#pragma unroll
            for (int nt = 0; nt < 8; nt++) {
                uint32_t b0 = __float_as_uint(W1s[(kb + tig) * 72 + nt * 8 + gid]);
                uint32_t b1 = __float_as_uint(W1s[(kb + tig + 4) * 72 + nt * 8 + gid]);
                mma8(acc[nt], a0, a1, a2, a3, b0, b1);
            }
        }
        __syncthreads();
    }

    const int r0 = row0 + w * 16 + gid;
    const int r1 = r0 + 8;
    const float m0 = (r0 < NNODE) ? 1.f : 0.f;
    const float m1 = (r1 < NNODE) ? 1.f : 0.f;

    float part = 0.f;
#pragma unroll
    for (int nt = 0; nt < 8; nt++) {
        int c = nt * 8 + tig * 2;
        float bb0 = sa_b1[c], bb1 = sa_b1[c + 1];
        float w20 = sa_w2[c], w21 = sa_w2[c + 1];
        part += m0 * (tanhfast(acc[nt][0] + bb0) * w20 + tanhfast(acc[nt][1] + bb1) * w21);
        part += m1 * (tanhfast(acc[nt][2] + bb0) * w20 + tanhfast(acc[nt][3] + bb1) * w21);
    }
#pragma unroll
    for (int o = 16; o > 0; o >>= 1) part += __shfl_xor_sync(0xffffffffu, part, o);
    if (lane == 0) atomicAdd(&s_sum, part);
    __syncthreads();
    if (tid == 0) atomicAdd(&g_wsum[p], s_sum);
}

// ---------------- K6: final weighted sum (4 elems/thread) ----------------
__global__ void k_final(float* __restrict__ out) {
    int i4 = blockIdx.x * blockDim.x + threadIdx.x;
    if (i4 >= NNODE * HD / 4) return;
    float w0 = g_wsum[0] * (1.f / NNODE);
    float w1 = g_wsum[1] * (1.f / NNODE);
    float w2 = g_wsum[2] * (1.f / NNODE);
    float mx = fmaxf(w0, fmaxf(w1, w2));
    float b0 = __expf(w0 - mx), b1 = __expf(w1 - mx), b2 = __expf(w2 - mx);
    float inv = 1.f / (b0 + b1 + b2);
    b0 *= inv; b1 *= inv; b2 *= inv;
    size_t idx = (size_t)i4 * 4;
    uint2 h0 = *(const uint2*)&g_zh[idx];
    uint2 h1 = *(const uint2*)&g_zh[(size_t)NNODE * HD + idx];
    uint2 h2 = *(const uint2*)&g_zh[(size_t)2 * NNODE * HD + idx];
    float2 z0a = __half22float2(*(__half2*)&h0.x), z0b = __half22float2(*(__half2*)&h0.y);
    float2 z1a = __half22float2(*(__half2*)&h1.x), z1b = __half22float2(*(__half2*)&h1.y);
    float2 z2a = __half22float2(*(__half2*)&h2.x), z2b = __half22float2(*(__half2*)&h2.y);
    float4 o;
    o.x = b0 * z0a.x + b1 * z1a.x + b2 * z2a.x;
    o.y = b0 * z0a.y + b1 * z1a.y + b2 * z2a.y;
    o.z = b0 * z0b.x + b1 * z1b.x + b2 * z2b.x;
    o.w = b0 * z0b.y + b1 * z1b.y + b2 * z2b.y;
    *(float4*)&out[idx] = o;
}

// ---------------- launch ----------------
extern "C" void kernel_launch(void* const* d_in, const int* in_sizes, int n_in,
                              void* d_out, int out_size) {
    const float* h    = (const float*)d_in[0];
    const int*   esrc = (const int*)d_in[1];
    const int*   edst = (const int*)d_in[2];
    const float* W    = (const float*)d_in[3];
    const float* al   = (const float*)d_in[4];
    const float* ar   = (const float*)d_in[5];
    const float* bias = (const float*)d_in[6];
    const float* w1   = (const float*)d_in[7];
    const float* b1   = (const float*)d_in[8];
    const float* w2   = (const float*)d_in[9];
    float* out = (float*)d_out;

    static cudaStream_t s2 = nullptr;
    static cudaEvent_t ev_fork = nullptr, ev_csr = nullptr, ev_sem = nullptr;
    static cudaEvent_t ev_p[NP] = {nullptr, nullptr, nullptr};
    if (s2 == nullptr) {
        cudaStreamCreateWithFlags(&s2, cudaStreamNonBlocking);
        cudaEventCreateWithFlags(&ev_fork, cudaEventDisableTiming);
        cudaEventCreateWithFlags(&ev_csr, cudaEventDisableTiming);
        cudaEventCreateWithFlags(&ev_sem, cudaEventDisableTiming);
        for (int p = 0; p < NP; p++)
            cudaEventCreateWithFlags(&ev_p[p], cudaEventDisableTiming);
        cudaFuncSetAttribute(k_gemm, cudaFuncAttributeMaxDynamicSharedMemorySize, GEMM_SMEM);
    }

    // fork: CSR chain on s2, monolithic gemm on main.
    cudaEventRecord(ev_fork, 0);
    cudaStreamWaitEvent(s2, ev_fork, 0);

    k_init<<<(PN + 255) / 256, 256, 0, s2>>>();
    k_count<<<(PE + 255) / 256, 256, 0, s2>>>(edst);
    k_scan_blocks<<<NB, 256, 0, s2>>>();

    k_gemm<<<MBLK, 256, GEMM_SMEM>>>(h, W, al, ar);

    k_scan_bsums<<<1, 512, 0, s2>>>();
    k_scan_final<<<NB, 256, 0, s2>>>();
    k_scatter<<<(PE + 255) / 256, 256, 0, s2>>>(esrc, edst);
    cudaEventRecord(ev_csr, s2);

    // join CSR into main, then per-p aggregate with sem pipelined on s2
    cudaStreamWaitEvent(0, ev_csr, 0);
    for (int p = 0; p < NP; p++) {
        k_p2<<<P2BLK, 256>>>(bias, p);
        cudaEventRecord(ev_p[p], 0);
        cudaStreamWaitEvent(s2, ev_p[p], 0);
        k_sem<<<MBLK, 256, 0, s2>>>(w1, b1, w2, p);
    }
    cudaEventRecord(ev_sem, s2);

    cudaStreamWaitEvent(0, ev_sem, 0);
    k_final<<<(NNODE * HD / 4 + 255) / 256, 256>>>(out);
}